// round 14
// baseline (speedup 1.0000x reference)
#include <cuda_runtime.h>
#include <cuda_fp16.h>
#include <cstdint>

#define NA 256
#define NB 256
#define NV 12
#define ND 512
#define NC 8
#define NW 64
#define NH 256
#define TEMP_INV 0.2f

// ---- scratch (device globals; no allocation allowed) ----
__device__ __align__(16) float g_P[NB * NV * NC * NH];   // 25 MB [b][v][c][h]
__device__ __align__(16) __half g_Th[NA * NC * NH];      // 1 MB  packed fp16 Tpart
__device__ float g_invn[NA * NC];                        // 1/||t_chunk||
__device__ float g_G[NB * NC * NV * NV];                 // 1.2 MB chunk Gram
__device__ __align__(16) float g_w[NB * NA * NV];        // 3 MB softmax weights
__device__ __align__(16) float g_cos[NB * NA * NC];      // 2 MB cosine logits

// ---- packed f32x2 helpers ----
__device__ __forceinline__ unsigned long long pk2(float lo, float hi) {
    unsigned long long r;
    asm("mov.b64 %0, {%1, %2};" : "=l"(r) : "f"(lo), "f"(hi));
    return r;
}
__device__ __forceinline__ void upk2(unsigned long long p, float& lo, float& hi) {
    asm("mov.b64 {%0, %1}, %2;" : "=f"(lo), "=f"(hi) : "l"(p));
}
__device__ __forceinline__ unsigned long long ffma2(unsigned long long a, unsigned long long b,
                                                    unsigned long long c) {
    unsigned long long d;
    asm("fma.rn.f32x2 %0, %1, %2, %3;" : "=l"(d) : "l"(a), "l"(b), "l"(c));
    return d;
}
__device__ __forceinline__ float warp_sum(float x) {
#pragma unroll
    for (int off = 16; off; off >>= 1) x += __shfl_xor_sync(0xffffffffu, x, off);
    return x;
}

// ---- cp.async helpers ----
__device__ __forceinline__ void cp16(uint32_t dst_smem, const void* src) {
    asm volatile("cp.async.cg.shared.global [%0], [%1], 16;" :: "r"(dst_smem), "l"(src));
}
__device__ __forceinline__ void cp_commit() {
    asm volatile("cp.async.commit_group;");
}
template <int N>
__device__ __forceinline__ void cp_wait() {
    asm volatile("cp.async.wait_group %0;" :: "n"(N));
}

// ================= kernel 1: prologue (512 mixed blocks — measured best) =================
__global__ __launch_bounds__(256, 2) void k_pre(const float* __restrict__ text,
                                                const float* __restrict__ video,
                                                const float* __restrict__ W1,
                                                const float* __restrict__ b1) {
    __shared__ __align__(16) float sm[NV * ND];
    const int bid = blockIdx.x, t = threadIdx.x;

    if (bid < NB) {
        const int b = bid;
        {
            const float4* vsrc = (const float4*)(video + b * NV * ND);
            float4* vdst = (float4*)sm;
            for (int i = t; i < NV * ND / 4; i += 256) vdst[i] = __ldg(vsrc + i);
        }
        __syncthreads();

        unsigned long long w1p[NW / 2];
#pragma unroll
        for (int w = 0; w < NW / 2; w++)
            w1p[w] = pk2(__ldg(&W1[(NW + 2 * w) * NH + t]),
                         __ldg(&W1[(NW + 2 * w + 1) * NH + t]));

        for (int v = 0; v < NV; v++) {
#pragma unroll
            for (int c = 0; c < NC; c++) {
                unsigned long long accA = 0ULL, accB = 0ULL;
                const ulonglong2* vr = (const ulonglong2*)(sm + v * ND + c * NW);
#pragma unroll
                for (int q = 0; q < NW / 4; q++) {
                    ulonglong2 x = vr[q];
                    accA = ffma2(x.x, w1p[2 * q], accA);
                    accB = ffma2(x.y, w1p[2 * q + 1], accB);
                }
                float a0, a1, b0, b1;
                upk2(accA, a0, a1); upk2(accB, b0, b1);
                g_P[((b * NV + v) * NC + c) * NH + t] = (a0 + b0) + (a1 + b1);
            }
        }

        const int lane = t & 31;
        for (int idx = t; idx < NC * NV * NV; idx += 256) {
            int c  = idx / (NV * NV);
            int r  = idx % (NV * NV);
            int v1 = r / NV, v2 = r % NV;
            const float* p1 = sm + v1 * ND + c * NW;
            const float* p2 = sm + v2 * ND + c * NW;
            float acc = 0.0f;
#pragma unroll
            for (int w0 = 0; w0 < NW; w0++) {
                int w = (w0 + lane * 2) & (NW - 1);
                acc = fmaf(p1[w], p2[w], acc);
            }
            g_G[b * NC * NV * NV + idx] = acc;
        }
    } else {
        const int a = bid - NB;
        float* trow  = sm;
        float* stage = sm + 512;
        trow[t]       = text[a * ND + t];
        trow[t + 256] = text[a * ND + 256 + t];
        __syncthreads();

        float w1t[NW];
#pragma unroll
        for (int w = 0; w < NW; w++) w1t[w] = __ldg(&W1[w * NH + t]);
        const float bb = __ldg(&b1[t]);
        const int kk = t >> 5, lane = t & 31;

#pragma unroll
        for (int c = 0; c < NC; c++) {
            float acc = bb;
#pragma unroll
            for (int w = 0; w < NW; w++) acc = fmaf(trow[c * NW + w], w1t[w], acc);
            stage[c * 264 + kk * 33 + lane] = acc;
        }

        float x1 = trow[kk * NW + lane];
        float x2 = trow[kk * NW + 32 + lane];
        float s = warp_sum(x1 * x1 + x2 * x2);
        if (lane == 0) g_invn[a * NC + kk] = rsqrtf(s);
        __syncthreads();

        for (int i = t; i < NC * NH; i += 256) {
            int c = i >> 8, r = i & 255;
            g_Th[a * (NC * NH) + i] = __float2half_rn(stage[c * 264 + (r & 7) * 33 + (r >> 3)]);
        }
    }
}

// ================= kernel 2: scores + softmax + cosine — 32-a tiles, 3 CTAs/SM =================
// grid (8, NB), 256 threads. Warp = frame-group g = t>>5 (uniform); al = t&31.
// g covers frame g, plus frame 8+g when g<4.
#define AT 32
#define TROW 68
#define TBUF (AT * TROW)  // 2176 floats per buffer, 3 buffers
#define OFF_V    6528
#define OFF_G    12672
#define OFF_W    13824
#define OFF_INVN 14208
#define OFF_LGT  14464
#define OFF_NP   14880
#define SCORE_SMEM_BYTES (16960 * 4)

__global__ __launch_bounds__(256, 3) void k_score(const float* __restrict__ text,
                                                  const float* __restrict__ video) {
    extern __shared__ __align__(16) float dyn[];
    float* T_sh    = dyn;
    float* V_sh    = dyn + OFF_V;
    float* G_sh    = dyn + OFF_G;
    float* w_sh    = dyn + OFF_W;
    float* invn_sh = dyn + OFF_INVN;
    float* logit_sh= dyn + OFF_LGT;   // [32][13]
    float* np_sh   = dyn + OFF_NP;    // [32][65]

    const int t = threadIdx.x;
    const int b = blockIdx.y;
    const int a0 = blockIdx.x * AT;
    const int al = t & 31, g = t >> 5;        // warp-uniform frame group
    const int f0 = g, f1 = 8 + g;             // f1 valid when g < 4

    // T staging: row lrow (0..31), 8-float segment seg (0..7) -> 2 cp16 per chunk
    const int lrow = t >> 3, seg = t & 7;
    const float* tg = text + (a0 + lrow) * ND + seg * 8;
    uint32_t ts_addr[3];
#pragma unroll
    for (int bu = 0; bu < 3; bu++)
        ts_addr[bu] = (uint32_t)__cvta_generic_to_shared(
            &T_sh[bu * TBUF + lrow * TROW + seg * 8]);

    // prologue: prefetch chunks 0,1
#pragma unroll
    for (int k = 0; k < 2; k++) cp16(ts_addr[0] + k * 16, tg + k * 4);
    cp_commit();
#pragma unroll
    for (int k = 0; k < 2; k++) cp16(ts_addr[1] + k * 16, tg + NW + k * 4);
    cp_commit();

    {
        const float4* vsrc = (const float4*)(video + b * NV * ND);
        float4* vdst = (float4*)V_sh;
        for (int i = t; i < NV * ND / 4; i += 256) vdst[i] = __ldg(vsrc + i);
    }
    for (int i = t; i < NC * NV * NV; i += 256) G_sh[i] = g_G[b * NC * NV * NV + i];
    if (t < AT * NC) invn_sh[t] = g_invn[a0 * NC + t];

    float S0[NC], S1[NC];
#pragma unroll
    for (int c = 0; c < NC; c++) { S0[c] = 0.0f; S1[c] = 0.0f; }

#pragma unroll
    for (int c = 0; c < NC; c++) {
        if (c < 7) cp_wait<1>(); else cp_wait<0>();
        __syncthreads();
        if (c < 6) {
            int nb = (c + 2) % 3;
#pragma unroll
            for (int k = 0; k < 2; k++) cp16(ts_addr[nb] + k * 16, tg + (c + 2) * NW + k * 4);
            cp_commit();
        }

        const float* Tb = T_sh + (c % 3) * TBUF;
        unsigned long long a0A = 0ULL, a0B = 0ULL, a1A = 0ULL, a1B = 0ULL;
#pragma unroll
        for (int q = 0; q < 16; q++) {
            ulonglong2 tr = *(const ulonglong2*)&Tb[al * TROW + q * 4];
            ulonglong2 v0 = *(const ulonglong2*)&V_sh[f0 * ND + c * NW + q * 4];
            a0A = ffma2(tr.x, v0.x, a0A);
            a0B = ffma2(tr.y, v0.y, a0B);
            if (g < 4) {
                ulonglong2 v1 = *(const ulonglong2*)&V_sh[f1 * ND + c * NW + q * 4];
                a1A = ffma2(tr.x, v1.x, a1A);
                a1B = ffma2(tr.y, v1.y, a1B);
            }
        }
        {
            float x0, x1, y0, y1;
            upk2(a0A, x0, x1); upk2(a0B, y0, y1);
            S0[c] = (x0 + y0) + (x1 + y1);
            if (g < 4) {
                upk2(a1A, x0, x1); upk2(a1B, y0, y1);
                S1[c] = (x0 + y0) + (x1 + y1);
            }
        }
    }

    // per-frame logits
    {
        float l0 = 0.0f, l1 = 0.0f;
#pragma unroll
        for (int c = 0; c < NC; c++) { l0 += S0[c]; l1 += S1[c]; }
        logit_sh[al * 13 + f0] = l0;
        if (g < 4) logit_sh[al * 13 + f1] = l1;
    }
    __syncthreads();

    if (t < AT) {  // softmax over v
        float s[NV], m = -1e30f;
#pragma unroll
        for (int v = 0; v < NV; v++) {
            s[v] = logit_sh[t * 13 + v] * TEMP_INV;
            m = fmaxf(m, s[v]);
        }
        float tot = 0.0f;
#pragma unroll
        for (int v = 0; v < NV; v++) { s[v] = __expf(s[v] - m); tot += s[v]; }
        float inv = 1.0f / tot;
#pragma unroll
        for (int v = 0; v < NV; v++) w_sh[t * NV + v] = s[v] * inv;
    }
    __syncthreads();

    // cosine numerator partials
    {
        float wj0 = w_sh[al * NV + f0];
        float wj1 = (g < 4) ? w_sh[al * NV + f1] : 0.0f;
#pragma unroll
        for (int c = 0; c < NC; c++)
            np_sh[al * 65 + g * 8 + c] = fmaf(wj1, S1[c], wj0 * S0[c]);
    }
    __syncthreads();

    // finish cosine: 256 (a,c) tasks, one per thread
    {
        int aa = t >> 3, cc = t & 7;
        float wv[NV];
#pragma unroll
        for (int v = 0; v < NV; v++) wv[v] = w_sh[aa * NV + v];
        float num = 0.0f;
#pragma unroll
        for (int gg = 0; gg < 8; gg++) num += np_sh[aa * 65 + gg * 8 + cc];
        float den = 0.0f;
#pragma unroll
        for (int v1 = 0; v1 < NV; v1++) {
            float ds = 0.0f;
#pragma unroll
            for (int v2 = 0; v2 < NV; v2++)
                ds = fmaf(wv[v2], G_sh[cc * NV * NV + v1 * NV + v2], ds);
            den = fmaf(wv[v1], ds, den);
        }
        g_cos[(b * NA + a0 + aa) * NC + cc] = num * invn_sh[aa * NC + cc] * rsqrtf(den);
    }
    // FIXED: strided write covers all AT*NV = 384 entries (was dropping 256..383)
    for (int i = t; i < AT * NV; i += 256)
        g_w[(b * NA + a0) * NV + i] = w_sh[i];
}

// ================= kernel 3: MLP gating (512 thr, f32x2, fp16 T loads) =================
__global__ __launch_bounds__(512, 1) void k_main(const float* __restrict__ W2,
                                                 const float* __restrict__ b2,
                                                 float* __restrict__ out) {
    __shared__ __align__(16) float2 wd_sh[64 * NV];
    __shared__ float cos_sh[64 * NC];
    __shared__ float part_sh[64][64];

    const int t = threadIdx.x;
    const int b = blockIdx.y;
    const int a0 = blockIdx.x * 64;
    const int lane = t & 31, w16 = t >> 5;
    const int c = w16 >> 1, half_ = w16 & 1;

    for (int i = t; i < 64 * NV; i += 512) {
        float wv = g_w[(b * NA + a0) * NV + i];
        wd_sh[i] = make_float2(wv, wv);
    }
    for (int i = t; i < 64 * NC; i += 512) cos_sh[i] = g_cos[(b * NA + a0) * NC + i];

    unsigned long long pp[NV][2];
#pragma unroll
    for (int v = 0; v < NV; v++)
#pragma unroll
        for (int jp = 0; jp < 2; jp++) {
            const float* base = &g_P[((b * NV + v) * NC + c) * NH + lane];
            pp[v][jp] = pk2(base[32 * (half_ * 4 + 2 * jp)], base[32 * (half_ * 4 + 2 * jp + 1)]);
        }
    float w2r[4];
#pragma unroll
    for (int j = 0; j < 4; j++) w2r[j] = __ldg(&W2[32 * (half_ * 4 + j) + lane]);
    const float b2v = __ldg(&b2[0]);
    __syncthreads();

    const __half* tb = g_Th + (a0 * NC + c) * NH + lane * 8 + half_ * 4;
    uint2 t0 = *(const uint2*)tb;
    uint2 t1 = *(const uint2*)(tb + NC * NH);

#pragma unroll 2
    for (int ia = 0; ia < 64; ia++) {
        uint2 cur = t0;
        t0 = t1;
        int nia = (ia < 62) ? ia + 2 : 63;
        t1 = *(const uint2*)(tb + nia * (NC * NH));

        float2 lo = __half22float2(*(__half2*)&cur.x);
        float2 hi = __half22float2(*(__half2*)&cur.y);
        unsigned long long a01 = pk2(lo.x, lo.y);
        unsigned long long a23 = pk2(hi.x, hi.y);

        const ulonglong2* wrow = (const ulonglong2*)&wd_sh[ia * NV];
#pragma unroll
        for (int vq = 0; vq < 6; vq++) {
            ulonglong2 wp = wrow[vq];
            a01 = ffma2(wp.x, pp[2 * vq][0], a01);
            a23 = ffma2(wp.x, pp[2 * vq][1], a23);
            a01 = ffma2(wp.y, pp[2 * vq + 1][0], a01);
            a23 = ffma2(wp.y, pp[2 * vq + 1][1], a23);
        }
        float f0, f1, f2, f3;
        upk2(a01, f0, f1); upk2(a23, f2, f3);
        float gg = fmaxf(f0, 0.0f) * w2r[0];
        gg = fmaf(fmaxf(f1, 0.0f), w2r[1], gg);
        gg = fmaf(fmaxf(f2, 0.0f), w2r[2], gg);
        gg = fmaf(fmaxf(f3, 0.0f), w2r[3], gg);
        gg += __shfl_xor_sync(0xffffffffu, gg, 16);
        gg += __shfl_xor_sync(0xffffffffu, gg, 8);
        gg += __shfl_xor_sync(0xffffffffu, gg, 4);
        if (lane < 4) part_sh[ia][w16 * 4 + lane] = gg;
    }
    __syncthreads();

    if (t < 64) {
        float sum = 0.0f;
#pragma unroll
        for (int c2 = 0; c2 < NC; c2++) {
            const float* pr = &part_sh[t][c2 * 8];
            float gsum = ((pr[0] + pr[1]) + (pr[2] + pr[3])) +
                         ((pr[4] + pr[5]) + (pr[6] + pr[7]));
            sum += (gsum + b2v) * cos_sh[t * NC + c2];
        }
        out[(a0 + t) * NB + b] = sum;
    }
}

extern "C" void kernel_launch(void* const* d_in, const int* in_sizes, int n_in,
                              void* d_out, int out_size) {
    const float* text  = (const float*)d_in[0];
    const float* video = (const float*)d_in[1];
    const float* W1    = (const float*)d_in[2];
    const float* b1    = (const float*)d_in[3];
    const float* W2    = (const float*)d_in[4];
    const float* b2    = (const float*)d_in[5];
    float* out = (float*)d_out;

    cudaFuncSetAttribute(k_score, cudaFuncAttributeMaxDynamicSharedMemorySize,
                         SCORE_SMEM_BYTES);

    k_pre<<<NB + NA, 256>>>(text, video, W1, b1);
    k_score<<<dim3(8, NB), 256, SCORE_SMEM_BYTES>>>(text, video);
    k_main<<<dim3(4, NB), 512>>>(W2, b2, out);
}

// round 15
// speedup vs baseline: 1.2065x; 1.2065x over previous
#include <cuda_runtime.h>
#include <cuda_fp16.h>
#include <cstdint>

#define NA 256
#define NB 256
#define NV 12
#define ND 512
#define NC 8
#define NW 64
#define NH 256
#define TEMP_INV 0.2f

// ---- scratch (device globals; no allocation allowed) ----
__device__ __align__(16) float g_P[NB * NV * NC * NH];   // 25 MB [b][v][c][h]
__device__ __align__(16) __half g_Th[NA * NC * NH];      // 1 MB  packed fp16 Tpart
__device__ float g_invn[NA * NC];                        // 1/||t_chunk||
__device__ float g_G[NB * NC * NV * NV];                 // 1.2 MB chunk Gram

// ---- packed f32x2 helpers ----
__device__ __forceinline__ unsigned long long pk2(float lo, float hi) {
    unsigned long long r;
    asm("mov.b64 %0, {%1, %2};" : "=l"(r) : "f"(lo), "f"(hi));
    return r;
}
__device__ __forceinline__ void upk2(unsigned long long p, float& lo, float& hi) {
    asm("mov.b64 {%0, %1}, %2;" : "=f"(lo), "=f"(hi) : "l"(p));
}
__device__ __forceinline__ unsigned long long ffma2(unsigned long long a, unsigned long long b,
                                                    unsigned long long c) {
    unsigned long long d;
    asm("fma.rn.f32x2 %0, %1, %2, %3;" : "=l"(d) : "l"(a), "l"(b), "l"(c));
    return d;
}
__device__ __forceinline__ float warp_sum(float x) {
#pragma unroll
    for (int off = 16; off; off >>= 1) x += __shfl_xor_sync(0xffffffffu, x, off);
    return x;
}

// ---- cp.async helpers ----
__device__ __forceinline__ void cp16(uint32_t dst_smem, const void* src) {
    asm volatile("cp.async.cg.shared.global [%0], [%1], 16;" :: "r"(dst_smem), "l"(src));
}
__device__ __forceinline__ void cp_commit() {
    asm volatile("cp.async.commit_group;");
}
template <int N>
__device__ __forceinline__ void cp_wait() {
    asm volatile("cp.async.wait_group %0;" :: "n"(N));
}

// ================= kernel 1: prologue (512 mixed blocks — measured best) =================
__global__ __launch_bounds__(256, 2) void k_pre(const float* __restrict__ text,
                                                const float* __restrict__ video,
                                                const float* __restrict__ W1,
                                                const float* __restrict__ b1) {
    __shared__ __align__(16) float sm[NV * ND];
    const int bid = blockIdx.x, t = threadIdx.x;

    if (bid < NB) {
        const int b = bid;
        {
            const float4* vsrc = (const float4*)(video + b * NV * ND);
            float4* vdst = (float4*)sm;
            for (int i = t; i < NV * ND / 4; i += 256) vdst[i] = __ldg(vsrc + i);
        }
        __syncthreads();

        unsigned long long w1p[NW / 2];
#pragma unroll
        for (int w = 0; w < NW / 2; w++)
            w1p[w] = pk2(__ldg(&W1[(NW + 2 * w) * NH + t]),
                         __ldg(&W1[(NW + 2 * w + 1) * NH + t]));

        for (int v = 0; v < NV; v++) {
#pragma unroll
            for (int c = 0; c < NC; c++) {
                unsigned long long accA = 0ULL, accB = 0ULL;
                const ulonglong2* vr = (const ulonglong2*)(sm + v * ND + c * NW);
#pragma unroll
                for (int q = 0; q < NW / 4; q++) {
                    ulonglong2 x = vr[q];
                    accA = ffma2(x.x, w1p[2 * q], accA);
                    accB = ffma2(x.y, w1p[2 * q + 1], accB);
                }
                float a0, a1, b0, b1;
                upk2(accA, a0, a1); upk2(accB, b0, b1);
                g_P[((b * NV + v) * NC + c) * NH + t] = (a0 + b0) + (a1 + b1);
            }
        }

        const int lane = t & 31;
        for (int idx = t; idx < NC * NV * NV; idx += 256) {
            int c  = idx / (NV * NV);
            int r  = idx % (NV * NV);
            int v1 = r / NV, v2 = r % NV;
            const float* p1 = sm + v1 * ND + c * NW;
            const float* p2 = sm + v2 * ND + c * NW;
            float acc = 0.0f;
#pragma unroll
            for (int w0 = 0; w0 < NW; w0++) {
                int w = (w0 + lane * 2) & (NW - 1);
                acc = fmaf(p1[w], p2[w], acc);
            }
            g_G[b * NC * NV * NV + idx] = acc;
        }
    } else {
        const int a = bid - NB;
        float* trow  = sm;
        float* stage = sm + 512;
        trow[t]       = text[a * ND + t];
        trow[t + 256] = text[a * ND + 256 + t];
        __syncthreads();

        float w1t[NW];
#pragma unroll
        for (int w = 0; w < NW; w++) w1t[w] = __ldg(&W1[w * NH + t]);
        const float bb = __ldg(&b1[t]);
        const int kk = t >> 5, lane = t & 31;

#pragma unroll
        for (int c = 0; c < NC; c++) {
            float acc = bb;
#pragma unroll
            for (int w = 0; w < NW; w++) acc = fmaf(trow[c * NW + w], w1t[w], acc);
            stage[c * 264 + kk * 33 + lane] = acc;
        }

        float x1 = trow[kk * NW + lane];
        float x2 = trow[kk * NW + 32 + lane];
        float s = warp_sum(x1 * x1 + x2 * x2);
        if (lane == 0) g_invn[a * NC + kk] = rsqrtf(s);
        __syncthreads();

        for (int i = t; i < NC * NH; i += 256) {
            int c = i >> 8, r = i & 255;
            g_Th[a * (NC * NH) + i] = __float2half_rn(stage[c * 264 + (r & 7) * 33 + (r >> 3)]);
        }
    }
}

// ================= kernel 2: FUSED score+softmax+cosine+MLP (64-a, 256 thr, 2 CTAs/SM) =================
// Score phase: thread = (al = t&63, vg = t>>6); vg covers frames 3vg..3vg+2 (R9 shape).
// Main phase: warp = center c = t>>5, lane owns h = 32k+lane, k=0..7.
// Main-phase arrays (wd/cos/part) ALIAS the dead T triple-buffer region.
#define TROW 68
#define TBUF (64 * TROW)  // 4352 floats per buffer, 3 buffers
#define SCORE_SMEM_BYTES (24576 * 4)   // 96 KB — 2 CTAs/SM

__global__ __launch_bounds__(256, 2) void k_fused(const float* __restrict__ text,
                                                  const float* __restrict__ video,
                                                  const float* __restrict__ W2,
                                                  const float* __restrict__ b2,
                                                  float* __restrict__ out) {
    extern __shared__ __align__(16) float dyn[];
    float* T_sh    = dyn;                // [0, 13056)  score phase only
    float* V_sh    = dyn + 13056;        // 6144
    float* G_sh    = dyn + 19200;        // 1152
    float* w_sh    = dyn + 20352;        // 768
    float* invn_sh = dyn + 21120;        // 512
    float* logit_sh= dyn + 21632;        // 832
    float* np_sh   = dyn + 22464;        // 2112
    // main-phase aliases into dead T region:
    float2* wd_sh  = (float2*)dyn;       // [0, 1536) floats
    float* cos_sh  = dyn + 1536;         // [1536, 2048)
    float* part_sh = dyn + 2048;         // [2048, 4096)  [ia][32]

    const int t = threadIdx.x;
    const int b = blockIdx.y;
    const int a0 = blockIdx.x * 64;
    const int al = t & 63, vg = t >> 6;

    // ---------- score phase (R9 3-stage pipeline, verbatim) ----------
    const int lrow = t >> 2, lpart = t & 3;
    const float* tg = text + (a0 + lrow) * ND + lpart * 16;
    uint32_t ts_addr[3];
#pragma unroll
    for (int bu = 0; bu < 3; bu++)
        ts_addr[bu] = (uint32_t)__cvta_generic_to_shared(
            &T_sh[bu * TBUF + lrow * TROW + lpart * 16]);

#pragma unroll
    for (int k = 0; k < 4; k++) cp16(ts_addr[0] + k * 16, tg + k * 4);
    cp_commit();
#pragma unroll
    for (int k = 0; k < 4; k++) cp16(ts_addr[1] + k * 16, tg + NW + k * 4);
    cp_commit();

    {
        const float4* vsrc = (const float4*)(video + b * NV * ND);
        float4* vdst = (float4*)V_sh;
        for (int i = t; i < NV * ND / 4; i += 256) vdst[i] = __ldg(vsrc + i);
    }
    for (int i = t; i < NC * NV * NV; i += 256) G_sh[i] = g_G[b * NC * NV * NV + i];
    for (int i = t; i < 64 * NC; i += 256) invn_sh[i] = g_invn[a0 * NC + i];

    float S[3][NC];
#pragma unroll
    for (int c = 0; c < NC; c++) {
        if (c < 7) cp_wait<1>(); else cp_wait<0>();
        __syncthreads();
        if (c < 6) {
            int nb = (c + 2) % 3;
#pragma unroll
            for (int k = 0; k < 4; k++) cp16(ts_addr[nb] + k * 16, tg + (c + 2) * NW + k * 4);
            cp_commit();
        }

        const float* Tb = T_sh + (c % 3) * TBUF;
        unsigned long long accA[3] = {0ULL, 0ULL, 0ULL};
        unsigned long long accB[3] = {0ULL, 0ULL, 0ULL};
#pragma unroll
        for (int q = 0; q < 16; q++) {
            ulonglong2 tr = *(const ulonglong2*)&Tb[al * TROW + q * 4];
#pragma unroll
            for (int j = 0; j < 3; j++) {
                ulonglong2 vd = *(const ulonglong2*)&V_sh[(vg * 3 + j) * ND + c * NW + q * 4];
                accA[j] = ffma2(tr.x, vd.x, accA[j]);
                accB[j] = ffma2(tr.y, vd.y, accB[j]);
            }
        }
#pragma unroll
        for (int j = 0; j < 3; j++) {
            float x0, x1, y0, y1;
            upk2(accA[j], x0, x1); upk2(accB[j], y0, y1);
            S[j][c] = (x0 + y0) + (x1 + y1);
        }
    }

#pragma unroll
    for (int j = 0; j < 3; j++) {
        float l = 0.0f;
#pragma unroll
        for (int c = 0; c < NC; c++) l += S[j][c];
        logit_sh[al * 13 + vg * 3 + j] = l;
    }
    __syncthreads();   // also: last read of T_sh done -> alias region free

    if (t < 64) {
        float s[NV], m = -1e30f;
#pragma unroll
        for (int v = 0; v < NV; v++) {
            s[v] = logit_sh[t * 13 + v] * TEMP_INV;
            m = fmaxf(m, s[v]);
        }
        float tot = 0.0f;
#pragma unroll
        for (int v = 0; v < NV; v++) { s[v] = __expf(s[v] - m); tot += s[v]; }
        float inv = 1.0f / tot;
#pragma unroll
        for (int v = 0; v < NV; v++) w_sh[t * NV + v] = s[v] * inv;
    }
    __syncthreads();

    // duplicated weights for the main loop (into aliased region)
    for (int i = t; i < 64 * NV; i += 256) {
        float wv = w_sh[i];
        wd_sh[i] = make_float2(wv, wv);
    }

    // cosine numerator partials
    {
        float wj[3];
#pragma unroll
        for (int j = 0; j < 3; j++) wj[j] = w_sh[al * NV + vg * 3 + j];
#pragma unroll
        for (int c = 0; c < NC; c++) {
            float acc = wj[0] * S[0][c];
            acc = fmaf(wj[1], S[1][c], acc);
            acc = fmaf(wj[2], S[2][c], acc);
            np_sh[al * 33 + vg * 8 + c] = acc;
        }
    }
    __syncthreads();

    // finish cosine -> cos_sh (512 tasks over 256 threads)
    for (int idx = t; idx < 512; idx += 256) {
        int aa = idx >> 3, cc = idx & 7;
        float wv[NV];
#pragma unroll
        for (int v = 0; v < NV; v++) wv[v] = w_sh[aa * NV + v];
        float num = (np_sh[aa * 33 + cc] + np_sh[aa * 33 + 8 + cc]) +
                    (np_sh[aa * 33 + 16 + cc] + np_sh[aa * 33 + 24 + cc]);
        float den = 0.0f;
#pragma unroll
        for (int v1 = 0; v1 < NV; v1++) {
            float ds = 0.0f;
#pragma unroll
            for (int v2 = 0; v2 < NV; v2++)
                ds = fmaf(wv[v2], G_sh[cc * NV * NV + v1 * NV + v2], ds);
            den = fmaf(wv[v1], ds, den);
        }
        cos_sh[aa * NC + cc] = num * invn_sh[aa * NC + cc] * rsqrtf(den);
    }

    // ---------- main (MLP gating) phase ----------
    const int lane = t & 31, c = t >> 5;

    unsigned long long pp[NV][4];
#pragma unroll
    for (int v = 0; v < NV; v++) {
        const float* base = &g_P[((b * NV + v) * NC + c) * NH + lane];
#pragma unroll
        for (int j = 0; j < 4; j++)
            pp[v][j] = pk2(base[32 * (2 * j)], base[32 * (2 * j + 1)]);
    }
    float w2r[8];
#pragma unroll
    for (int k = 0; k < 8; k++) w2r[k] = __ldg(&W2[32 * k + lane]);
    const float b2v = __ldg(&b2[0]);
    __syncthreads();  // wd_sh/cos_sh ready

    const __half* tb = g_Th + (a0 * NC + c) * NH + lane * 8;  // 8 halves = 16B per a
    uint4 t0 = *(const uint4*)tb;
    uint4 t1 = *(const uint4*)(tb + NC * NH);

#pragma unroll 2
    for (int ia = 0; ia < 64; ia++) {
        uint4 cur = t0;
        t0 = t1;
        int nia = (ia < 62) ? ia + 2 : 63;
        t1 = *(const uint4*)(tb + nia * (NC * NH));

        float2 p0 = __half22float2(*(__half2*)&cur.x);
        float2 p1 = __half22float2(*(__half2*)&cur.y);
        float2 p2 = __half22float2(*(__half2*)&cur.z);
        float2 p3 = __half22float2(*(__half2*)&cur.w);
        unsigned long long acc0 = pk2(p0.x, p0.y);
        unsigned long long acc1 = pk2(p1.x, p1.y);
        unsigned long long acc2 = pk2(p2.x, p2.y);
        unsigned long long acc3 = pk2(p3.x, p3.y);

        const ulonglong2* wrow = (const ulonglong2*)&wd_sh[ia * NV];
#pragma unroll
        for (int vq = 0; vq < 6; vq++) {
            ulonglong2 wp = wrow[vq];
            acc0 = ffma2(wp.x, pp[2 * vq][0], acc0);
            acc1 = ffma2(wp.x, pp[2 * vq][1], acc1);
            acc2 = ffma2(wp.x, pp[2 * vq][2], acc2);
            acc3 = ffma2(wp.x, pp[2 * vq][3], acc3);
            acc0 = ffma2(wp.y, pp[2 * vq + 1][0], acc0);
            acc1 = ffma2(wp.y, pp[2 * vq + 1][1], acc1);
            acc2 = ffma2(wp.y, pp[2 * vq + 1][2], acc2);
            acc3 = ffma2(wp.y, pp[2 * vq + 1][3], acc3);
        }
        float f0, f1, f2, f3, f4, f5, f6, f7;
        upk2(acc0, f0, f1); upk2(acc1, f2, f3);
        upk2(acc2, f4, f5); upk2(acc3, f6, f7);
        float g = fmaxf(f0, 0.0f) * w2r[0];
        g = fmaf(fmaxf(f1, 0.0f), w2r[1], g);
        g = fmaf(fmaxf(f2, 0.0f), w2r[2], g);
        g = fmaf(fmaxf(f3, 0.0f), w2r[3], g);
        g = fmaf(fmaxf(f4, 0.0f), w2r[4], g);
        g = fmaf(fmaxf(f5, 0.0f), w2r[5], g);
        g = fmaf(fmaxf(f6, 0.0f), w2r[6], g);
        g = fmaf(fmaxf(f7, 0.0f), w2r[7], g);
        g += __shfl_xor_sync(0xffffffffu, g, 16);
        g += __shfl_xor_sync(0xffffffffu, g, 8);
        g += __shfl_xor_sync(0xffffffffu, g, 4);
        if (lane < 4) part_sh[ia * 32 + c * 4 + lane] = g;
    }
    __syncthreads();

    if (t < 64) {
        float sum = 0.0f;
#pragma unroll
        for (int c2 = 0; c2 < NC; c2++) {
            const float* pr = &part_sh[t * 32 + c2 * 4];
            float gsum = (pr[0] + pr[1]) + (pr[2] + pr[3]);
            sum += (gsum + b2v) * cos_sh[t * NC + c2];
        }
        out[(a0 + t) * NB + b] = sum;
    }
}

extern "C" void kernel_launch(void* const* d_in, const int* in_sizes, int n_in,
                              void* d_out, int out_size) {
    const float* text  = (const float*)d_in[0];
    const float* video = (const float*)d_in[1];
    const float* W1    = (const float*)d_in[2];
    const float* b1    = (const float*)d_in[3];
    const float* W2    = (const float*)d_in[4];
    const float* b2    = (const float*)d_in[5];
    float* out = (float*)d_out;

    cudaFuncSetAttribute(k_fused, cudaFuncAttributeMaxDynamicSharedMemorySize,
                         SCORE_SMEM_BYTES);

    k_pre<<<NB + NA, 256>>>(text, video, W1, b1);
    k_fused<<<dim3(4, NB), 256, SCORE_SMEM_BYTES>>>(text, video, W2, b2, out);
}